// round 6
// baseline (speedup 1.0000x reference)
#include <cuda_runtime.h>
#include <cstdint>

#define BN   32
#define CIN  256
#define COUT 256
#define HIN  64
#define WIN  64
#define OH   32
#define OW   32

#define ROW_S  72                   // floats per row in x stage
#define CI_S   1224                 // 17 rows * 72
#define SBUF   19584                // floats per buffer (16 planes + shift slack)
#define SM_BYTES (2 * SBUF * 4)     // 156672 B

#define NWA (9 * 32 * 16 * 128)     // weights: tap x ks x mtile x lane x 4

// Weights in mma-fragment order: [tap][ks][mt][lane][q], tf32-RNA rounded
__device__ __align__(16) float g_wA[NWA];

__device__ __forceinline__ uint32_t smem_u32(const void* p) {
    uint32_t a;
    asm("{ .reg .u64 t; cvta.to.shared.u64 t, %1; cvt.u32.u64 %0, t; }" : "=r"(a) : "l"(p));
    return a;
}

__global__ void prep_w(const float* __restrict__ w) {
    int idx = blockIdx.x * 256 + threadIdx.x;
    if (idx >= NWA) return;
    int q  = idx & 3;
    int l  = (idx >> 2) & 31;
    int mt = (idx >> 7) & 15;
    int ks = (idx >> 11) & 31;
    int t  = idx >> 16;
    int m  = mt * 16 + (l >> 2) + (q & 1) * 8;
    int ci = ks * 8 + (l & 3) + ((q >> 1) & 1) * 4;
    float v = w[((size_t)m * CIN + ci) * 9 + t];
    float o;
    asm("cvt.rna.tf32.f32 %0, %1;" : "=f"(o) : "f"(v));
    g_wA[idx] = o;
}

__global__ __launch_bounds__(256, 1)
void conv_mma(const float* __restrict__ x, float* __restrict__ out) {
    extern __shared__ __align__(16) float xs[];
    const int tid  = threadIdx.x;
    const int lane = tid & 31;
    const int warp = tid >> 5;
    const int warpM = warp >> 2;   // 0..1 : 64-cout slab
    const int warpN = warp & 3;    // 0..3 : 2 output rows each
    const int gid = lane >> 2;
    const int tig = lane & 3;
    const int bx = blockIdx.x;
    const int R  = blockIdx.y * 8;     // 8 output rows per CTA
    const int b  = blockIdx.z;

    const uint32_t xs_base = smem_u32(xs);

    // ---- fill x stage for group g into buffer buf (4B cp.async, zfill pads) ----
    auto fill = [&](int g, int buf) {
        const float* xg = x + ((size_t)b * CIN + g * 16) * (HIN * WIN);
        const uint32_t dstb = xs_base + buf * (SBUF * 4);
        if (tid < 272) {  // zero left-pad word (iw = -1 slot) per (ci,row)
            int ci = tid / 17, row = tid % 17;
            uint32_t d = dstb + (ci * CI_S + (ci & 1) + row * ROW_S + 3) * 4;
            asm volatile("st.shared.f32 [%0], 0f00000000;" :: "r"(d));
        }
        for (int i = tid; i < 16 * 17 * 64; i += 256) {
            int ci  = i / 1088;
            int rem = i % 1088;
            int row = rem >> 6, c = rem & 63;
            int ir  = 2 * R - 1 + row;
            uint32_t d = dstb + (ci * CI_S + (ci & 1) + row * ROW_S + 4 + c) * 4;
            const float* s = xg + (size_t)ci * (HIN * WIN) + ir * WIN + c;
            int sz = (ir >= 0) ? 4 : 0;
            asm volatile("cp.async.ca.shared.global [%0], [%1], 4, %2;"
                         :: "r"(d), "l"(s), "r"(sz));
        }
    };

    float acc[4][8][4];
#pragma unroll
    for (int mt = 0; mt < 4; mt++)
#pragma unroll
        for (int nt = 0; nt < 8; nt++)
#pragma unroll
            for (int q = 0; q < 4; q++) acc[mt][nt][q] = 0.f;

    fill(0, 0);
    asm volatile("cp.async.commit_group;" ::: "memory");
    asm volatile("cp.async.wait_group 0;" ::: "memory");
    __syncthreads();

    // thread-invariant part of B byte address
    const uint32_t tb0 = (uint32_t)(tig * CI_S + (tig & 1) + 4 * warpN * ROW_S + 3 + 2 * gid) * 4;
    const float4* Abase = (const float4*)g_wA;

    for (int g = 0; g < 16; g++) {
        if (g < 15) fill(g + 1, (g + 1) & 1);
        asm volatile("cp.async.commit_group;" ::: "memory");

        const uint32_t bufb = xs_base + (g & 1) * (SBUF * 4);

        // A prefetch for step 0
        uint4 A0, A1, A2, A3;
        {
            const float4* ap = Abase + ((size_t)((0 * 32 + g * 2 + 0) * 16 + bx * 8 + warpM * 4)) * 32 + lane;
            float4 f0 = ap[0], f1 = ap[32], f2 = ap[64], f3 = ap[96];
            A0 = *(uint4*)&f0; A1 = *(uint4*)&f1; A2 = *(uint4*)&f2; A3 = *(uint4*)&f3;
        }

#pragma unroll 2
        for (int step = 0; step < 18; step++) {
            const int t   = step >> 1;
            const int ksl = step & 1;
            const int kh  = t / 3;
            const int kw  = t % 3;

            // prefetch next step's A (clamped re-load on the last step)
            uint4 N0, N1, N2, N3;
            {
                int sn = (step < 17) ? step + 1 : 17;
                int tn = sn >> 1, kn = sn & 1;
                const float4* ap = Abase + ((size_t)((tn * 32 + g * 2 + kn) * 16 + bx * 8 + warpM * 4)) * 32 + lane;
                float4 f0 = ap[0], f1 = ap[32], f2 = ap[64], f3 = ap[96];
                N0 = *(uint4*)&f0; N1 = *(uint4*)&f1; N2 = *(uint4*)&f2; N3 = *(uint4*)&f3;
            }

            const uint32_t abase = bufb + tb0 + kh * 288 + kw * 4 + ksl * (8 * CI_S * 4);

#define MMA_ONE(ACC, A, B0, B1)                                                \
    asm volatile("mma.sync.aligned.m16n8k8.row.col.f32.tf32.tf32.f32 "         \
                 "{%0,%1,%2,%3},{%4,%5,%6,%7},{%8,%9},{%0,%1,%2,%3};"          \
                 : "+f"(ACC[0]), "+f"(ACC[1]), "+f"(ACC[2]), "+f"(ACC[3])      \
                 : "r"(A.x), "r"(A.y), "r"(A.z), "r"(A.w), "r"(B0), "r"(B1))
#pragma unroll
            for (int nt = 0; nt < 8; nt++) {
                const uint32_t ba = abase + (nt >> 2) * 576 + (nt & 3) * 64;
                float v0, v1;
                uint32_t b0, b1;
                asm volatile("ld.shared.f32 %0, [%1];" : "=f"(v0) : "r"(ba));
                asm volatile("ld.shared.f32 %0, [%1];" : "=f"(v1) : "r"(ba + 4 * CI_S * 4));
                asm("cvt.rna.tf32.f32 %0, %1;" : "=r"(b0) : "f"(v0));
                asm("cvt.rna.tf32.f32 %0, %1;" : "=r"(b1) : "f"(v1));
                MMA_ONE(acc[0][nt], A0, b0, b1);
                MMA_ONE(acc[1][nt], A1, b0, b1);
                MMA_ONE(acc[2][nt], A2, b0, b1);
                MMA_ONE(acc[3][nt], A3, b0, b1);
            }
#undef MMA_ONE
            A0 = N0; A1 = N1; A2 = N2; A3 = N3;
        }

        asm volatile("cp.async.wait_group 0;" ::: "memory");
        __syncthreads();
    }

    // ---------------- epilogue ----------------
#pragma unroll
    for (int mt = 0; mt < 4; mt++) {
        int co = bx * 128 + warpM * 64 + mt * 16 + gid;
#pragma unroll
        for (int nt = 0; nt < 8; nt++) {
            int orow = R + warpN * 2 + (nt >> 2);
            int ow0  = (nt & 3) * 8 + tig * 2;
            float* base = out + (((size_t)b * COUT + co) * OH + orow) * OW + ow0;
            *(float2*)base = make_float2(acc[mt][nt][0], acc[mt][nt][1]);
            *(float2*)(base + 8 * OH * OW) = make_float2(acc[mt][nt][2], acc[mt][nt][3]);
        }
    }
}

extern "C" void kernel_launch(void* const* d_in, const int* in_sizes, int n_in,
                              void* d_out, int out_size) {
    const float* x = (const float*)d_in[0];   // [32,256,64,64]
    const float* w = (const float*)d_in[1];   // [256,256,3,3]
    float* out = (float*)d_out;               // [32,256,32,32]
    (void)in_sizes; (void)n_in; (void)out_size;

    cudaFuncSetAttribute(conv_mma, cudaFuncAttributeMaxDynamicSharedMemorySize, SM_BYTES);

    prep_w<<<(NWA + 255) / 256, 256>>>(w);

    dim3 grid(2, 4, BN);  // 256 CTAs, 1/SM, ~1.73 waves
    conv_mma<<<grid, 256, SM_BYTES>>>(x, out);
}

// round 7
// speedup vs baseline: 1.5170x; 1.5170x over previous
#include <cuda_runtime.h>
#include <cstdint>

#define BN   32
#define CIN  256
#define COUT 256
#define HIN  64
#define WIN  64
#define OH   32
#define OW   32

#define ROW_S  72                  // floats per row in x stage
#define CI_S   648                 // 9 rows * 72
#define SBUF   10368               // 16 ci planes per buffer
#define SM_BYTES (2 * SBUF * 4)    // 82944 B

#define NWA (9 * 32 * 16 * 128)    // weights: tap x ks x mt x lane x 4

// Weights in mma-fragment order: [tap][ks][mt][lane][q], tf32-RNA rounded
__device__ __align__(16) float g_wA[NWA];

__device__ __forceinline__ uint32_t smem_u32(const void* p) {
    uint32_t a;
    asm("{ .reg .u64 t; cvta.to.shared.u64 t, %1; cvt.u32.u64 %0, t; }" : "=r"(a) : "l"(p));
    return a;
}

__global__ void prep_w(const float* __restrict__ w) {
    int idx = blockIdx.x * 256 + threadIdx.x;
    if (idx >= NWA) return;
    int q  = idx & 3;
    int l  = (idx >> 2) & 31;
    int mt = (idx >> 7) & 15;
    int ks = (idx >> 11) & 31;
    int t  = idx >> 16;
    int m  = mt * 16 + (l >> 2) + (q & 1) * 8;
    int ci = ks * 8 + (l & 3) + ((q >> 1) & 1) * 4;
    float v = w[((size_t)m * CIN + ci) * 9 + t];
    float o;
    asm("cvt.rna.tf32.f32 %0, %1;" : "=f"(o) : "f"(v));
    g_wA[idx] = o;
}

// CTA: m256 (all couts) x n128 (4 output rows). 512 threads, 16 warps,
// warp tile m64n32. Double-buffered x stage, one ci-group (16) per buffer.
__global__ __launch_bounds__(512, 1)
void conv_mma(const float* __restrict__ x, float* __restrict__ out) {
    extern __shared__ __align__(16) float xs[];
    const int tid  = threadIdx.x;
    const int lane = tid & 31;
    const int warp = tid >> 5;
    const int warpM = warp >> 2;     // 0..3 : 64-cout slab
    const int warpN = warp & 3;      // 0..3 : output row within tile
    const int gid = lane >> 2;
    const int tig = lane & 3;
    const int R  = blockIdx.x * 4;   // 4 output rows per CTA
    const int b  = blockIdx.y;

    const uint32_t xs_base = smem_u32(xs);

    // zero the iw=-1 pad word (float idx 3) once per (ci,row) in both buffers
    if (tid < 288) {
        int bf = tid >= 144;
        int r144 = tid - bf * 144;
        int ci = r144 / 9, row = r144 % 9;
        uint32_t d = xs_base + (uint32_t)(bf * SBUF + ci * CI_S + row * ROW_S + 3) * 4;
        asm volatile("st.shared.f32 [%0], 0f00000000;" :: "r"(d));
    }
    __syncthreads();

    // ---- fill group g's x tile into buffer buf (16B cp.async, zfill top pad) ----
    auto fill = [&](int g, int buf) {
        const float* xg = x + ((size_t)b * CIN + g * 16) * (HIN * WIN);
        const uint32_t dstb = xs_base + (uint32_t)buf * (SBUF * 4);
        for (int i = tid; i < 2304; i += 512) {
            int ci  = i / 144;
            int rem = i % 144;
            int row = rem >> 4, c4 = rem & 15;
            int ir  = 2 * R - 1 + row;
            uint32_t d = dstb + (uint32_t)(ci * CI_S + row * ROW_S + 4 + 4 * c4) * 4;
            const float* s = xg + (size_t)ci * (HIN * WIN) + ir * WIN + 4 * c4;
            int sz = (ir >= 0) ? 16 : 0;
            asm volatile("cp.async.ca.shared.global [%0], [%1], 16, %2;"
                         :: "r"(d), "l"(s), "r"(sz));
        }
    };

    float acc[4][4][4];
#pragma unroll
    for (int mt = 0; mt < 4; mt++)
#pragma unroll
        for (int nt = 0; nt < 4; nt++)
#pragma unroll
            for (int q = 0; q < 4; q++) acc[mt][nt][q] = 0.f;

    fill(0, 0);
    asm volatile("cp.async.commit_group;" ::: "memory");
    fill(1, 1);
    asm volatile("cp.async.commit_group;" ::: "memory");

    // thread-invariant part of B byte address (within buffer)
    const uint32_t tb0 = (uint32_t)(tig * CI_S + 2 * warpN * ROW_S + 3 + 2 * gid) * 4;
    const float4* Abase = (const float4*)g_wA + (size_t)(warpM * 4) * 32 + lane;

    for (int g = 0; g < 16; g++) {
        if (g < 15) { asm volatile("cp.async.wait_group 1;" ::: "memory"); }
        else        { asm volatile("cp.async.wait_group 0;" ::: "memory"); }
        __syncthreads();

        const uint32_t bufb = xs_base + (uint32_t)(g & 1) * (SBUF * 4);

#pragma unroll 2
        for (int step = 0; step < 18; step++) {
            const int t   = step >> 1;
            const int ksl = step & 1;
            const int kh  = t / 3;
            const int kw  = t % 3;
            const int ks  = g * 2 + ksl;

            // A fragments: 4 coalesced LDG.128 (L2-resident stream)
            const float4* ap = Abase + (size_t)((t * 32 + ks) * 16) * 32;
            float4 f0 = ap[0], f1 = ap[32], f2 = ap[64], f3 = ap[96];
            uint4 A0 = *(uint4*)&f0, A1 = *(uint4*)&f1,
                  A2 = *(uint4*)&f2, A3 = *(uint4*)&f3;

            const uint32_t abase = bufb + tb0 +
                (uint32_t)(kh * ROW_S + kw + ksl * 8 * CI_S) * 4;

#define MMA_ONE(ACC, A, B0, B1)                                                \
    asm volatile("mma.sync.aligned.m16n8k8.row.col.f32.tf32.tf32.f32 "         \
                 "{%0,%1,%2,%3},{%4,%5,%6,%7},{%8,%9},{%0,%1,%2,%3};"          \
                 : "+f"(ACC[0]), "+f"(ACC[1]), "+f"(ACC[2]), "+f"(ACC[3])      \
                 : "r"(A.x), "r"(A.y), "r"(A.z), "r"(A.w), "r"(B0), "r"(B1))
#pragma unroll
            for (int nt = 0; nt < 4; nt++) {
                const uint32_t ba = abase + nt * 64;
                float v0, v1;
                uint32_t b0, b1;
                asm volatile("ld.shared.f32 %0, [%1];" : "=f"(v0) : "r"(ba));
                asm volatile("ld.shared.f32 %0, [%1];" : "=f"(v1) : "r"(ba + 4 * CI_S * 4));
                asm("cvt.rna.tf32.f32 %0, %1;" : "=r"(b0) : "f"(v0));
                asm("cvt.rna.tf32.f32 %0, %1;" : "=r"(b1) : "f"(v1));
                MMA_ONE(acc[0][nt], A0, b0, b1);
                MMA_ONE(acc[1][nt], A1, b0, b1);
                MMA_ONE(acc[2][nt], A2, b0, b1);
                MMA_ONE(acc[3][nt], A3, b0, b1);
            }
#undef MMA_ONE
        }

        __syncthreads();
        if (g < 14) {
            fill(g + 2, g & 1);
            asm volatile("cp.async.commit_group;" ::: "memory");
        }
    }

    // ---------------- epilogue ----------------
    const int orow = R + warpN;
#pragma unroll
    for (int mt = 0; mt < 4; mt++) {
        int co = warpM * 64 + mt * 16 + gid;
        float* base = out + (((size_t)b * COUT + co) * OH + orow) * OW;
#pragma unroll
        for (int nt = 0; nt < 4; nt++) {
            int ow0 = nt * 8 + tig * 2;
            *(float2*)(base + ow0) = make_float2(acc[mt][nt][0], acc[mt][nt][1]);
            *(float2*)(base + 8 * OH * OW + ow0) = make_float2(acc[mt][nt][2], acc[mt][nt][3]);
        }
    }
}

extern "C" void kernel_launch(void* const* d_in, const int* in_sizes, int n_in,
                              void* d_out, int out_size) {
    const float* x = (const float*)d_in[0];   // [32,256,64,64]
    const float* w = (const float*)d_in[1];   // [256,256,3,3]
    float* out = (float*)d_out;               // [32,256,32,32]
    (void)in_sizes; (void)n_in; (void)out_size;

    cudaFuncSetAttribute(conv_mma, cudaFuncAttributeMaxDynamicSharedMemorySize, SM_BYTES);

    prep_w<<<(NWA + 255) / 256, 256>>>(w);

    dim3 grid(8, BN);  // 8 row-tiles x 32 batch = 256 CTAs, 512 thr each
    conv_mma<<<grid, 512, SM_BYTES>>>(x, out);
}

// round 10
// speedup vs baseline: 1.5190x; 1.0013x over previous
#include <cuda_runtime.h>
#include <cstdint>

#define BN   32
#define CIN  256
#define COUT 256
#define HIN  64
#define WIN  64
#define OH   32
#define OW   32

#define ROW_S  72                  // floats per row in x stage
#define CI_S   648                 // 9 rows * 72
#define SBUF   10368               // 16 ci planes per buffer
#define NBUF   3
#define SM_BYTES (NBUF * SBUF * 4) // 124416 B

#define NWA (9 * 32 * 16 * 128)    // weights: tap x ks x mt x lane x 4

// Weights in mma-fragment order: [tap][ks][mt][lane][q], tf32-RNA rounded
__device__ __align__(16) float g_wA[NWA];

__device__ __forceinline__ uint32_t smem_u32(const void* p) {
    uint32_t a;
    asm("{ .reg .u64 t; cvta.to.shared.u64 t, %1; cvt.u32.u64 %0, t; }" : "=r"(a) : "l"(p));
    return a;
}

__global__ void prep_w(const float* __restrict__ w) {
    int idx = blockIdx.x * 256 + threadIdx.x;
    if (idx >= NWA) return;
    int q  = idx & 3;
    int l  = (idx >> 2) & 31;
    int mt = (idx >> 7) & 15;
    int ks = (idx >> 11) & 31;
    int t  = idx >> 16;
    int m  = mt * 16 + (l >> 2) + (q & 1) * 8;
    int ci = ks * 8 + (l & 3) + ((q >> 1) & 1) * 4;
    float v = w[((size_t)m * CIN + ci) * 9 + t];
    float o;
    asm("cvt.rna.tf32.f32 %0, %1;" : "=f"(o) : "f"(v));
    g_wA[idx] = o;
}

// CTA: m256 (all couts) x n128 (4 output rows). 512 threads, 16 warps,
// warp tile m64n32. Triple-buffered x stage, one ci-group (16) per buffer.
__global__ __launch_bounds__(512, 1)
void conv_mma(const float* __restrict__ x, float* __restrict__ out) {
    extern __shared__ __align__(16) float xs[];
    const int tid  = threadIdx.x;
    const int lane = tid & 31;
    const int warp = tid >> 5;
    const int warpM = warp >> 2;     // 0..3 : 64-cout slab
    const int warpN = warp & 3;      // 0..3 : output row within tile
    const int gid = lane >> 2;
    const int tig = lane & 3;
    const int R  = blockIdx.x * 4;   // 4 output rows per CTA
    const int b  = blockIdx.y;

    const uint32_t xs_base = smem_u32(xs);

    // zero the iw=-1 pad word (float idx 3) per (ci,row) in all 3 buffers
    if (tid < NBUF * 144) {
        int bf = tid / 144;
        int r144 = tid % 144;
        int ci = r144 / 9, row = r144 % 9;
        uint32_t d = xs_base + (uint32_t)(bf * SBUF + ci * CI_S + row * ROW_S + 3) * 4;
        asm volatile("st.shared.f32 [%0], 0f00000000;" :: "r"(d));
    }
    __syncthreads();

    // ---- fill group g's x tile into buffer buf (16B cp.async, zfill top pad) ----
    auto fill = [&](int g, int buf) {
        const float* xg = x + ((size_t)b * CIN + g * 16) * (HIN * WIN);
        const uint32_t dstb = xs_base + (uint32_t)buf * (SBUF * 4);
        for (int i = tid; i < 2304; i += 512) {
            int ci  = i / 144;
            int rem = i % 144;
            int row = rem >> 4, c4 = rem & 15;
            int ir  = 2 * R - 1 + row;
            uint32_t d = dstb + (uint32_t)(ci * CI_S + row * ROW_S + 4 + 4 * c4) * 4;
            const float* s = xg + (size_t)ci * (HIN * WIN) + ir * WIN + 4 * c4;
            int sz = (ir >= 0) ? 16 : 0;
            asm volatile("cp.async.ca.shared.global [%0], [%1], 16, %2;"
                         :: "r"(d), "l"(s), "r"(sz));
        }
        asm volatile("cp.async.commit_group;" ::: "memory");
    };

    float acc[4][4][4];
#pragma unroll
    for (int mt = 0; mt < 4; mt++)
#pragma unroll
        for (int nt = 0; nt < 4; nt++)
#pragma unroll
            for (int q = 0; q < 4; q++) acc[mt][nt][q] = 0.f;

    fill(0, 0);
    fill(1, 1);

    // thread-invariant part of B byte address (within buffer)
    const uint32_t tb0 = (uint32_t)(tig * CI_S + 2 * warpN * ROW_S + 3 + 2 * gid) * 4;
    const float4* Abase = (const float4*)g_wA + (size_t)(warpM * 4) * 32 + lane;

    int buf = 0;
    for (int g = 0; g < 16; g++) {
        asm volatile("cp.async.wait_group 1;" ::: "memory");
        __syncthreads();
        // overlap: start fill(g+2) into the buffer consumed at group g-1
        if (g < 14) {
            int nb = buf + 2;
            if (nb >= NBUF) nb -= NBUF;
            fill(g + 2, nb);
        }

        const uint32_t bufb = xs_base + (uint32_t)buf * (SBUF * 4);

#pragma unroll 2
        for (int step = 0; step < 18; step++) {
            const int t   = step >> 1;
            const int ksl = step & 1;
            const int kh  = t / 3;
            const int kw  = t % 3;
            const int ks  = g * 2 + ksl;

            // A fragments: 4 coalesced LDG.128 issued first (latency overlaps B block)
            const float4* ap = Abase + (size_t)((t * 32 + ks) * 16) * 32;
            float4 f0 = ap[0], f1 = ap[32], f2 = ap[64], f3 = ap[96];

            const uint32_t abase = bufb + tb0 +
                (uint32_t)(kh * ROW_S + kw + ksl * 8 * CI_S) * 4;

            // B: batch all 8 loads, then all 8 cvts (explicit MLP)
            float v0[4], v1[4];
#pragma unroll
            for (int nt = 0; nt < 4; nt++) {
                asm volatile("ld.shared.f32 %0, [%1];" : "=f"(v0[nt]) : "r"(abase + nt * 64));
                asm volatile("ld.shared.f32 %0, [%1];" : "=f"(v1[nt])
                             : "r"(abase + nt * 64 + 4 * CI_S * 4));
            }
            uint32_t b0[4], b1[4];
#pragma unroll
            for (int nt = 0; nt < 4; nt++) {
                asm("cvt.rna.tf32.f32 %0, %1;" : "=r"(b0[nt]) : "f"(v0[nt]));
                asm("cvt.rna.tf32.f32 %0, %1;" : "=r"(b1[nt]) : "f"(v1[nt]));
            }

            uint4 A0 = *(uint4*)&f0, A1 = *(uint4*)&f1,
                  A2 = *(uint4*)&f2, A3 = *(uint4*)&f3;

#define MMA_ONE(ACC, A, B0, B1)                                                \
    asm volatile("mma.sync.aligned.m16n8k8.row.col.f32.tf32.tf32.f32 "         \
                 "{%0,%1,%2,%3},{%4,%5,%6,%7},{%8,%9},{%0,%1,%2,%3};"          \
                 : "+f"(ACC[0]), "+f"(ACC[1]), "+f"(ACC[2]), "+f"(ACC[3])      \
                 : "r"(A.x), "r"(A.y), "r"(A.z), "r"(A.w), "r"(B0), "r"(B1))
#pragma unroll
            for (int nt = 0; nt < 4; nt++) {
                MMA_ONE(acc[0][nt], A0, b0[nt], b1[nt]);
                MMA_ONE(acc[1][nt], A1, b0[nt], b1[nt]);
                MMA_ONE(acc[2][nt], A2, b0[nt], b1[nt]);
                MMA_ONE(acc[3][nt], A3, b0[nt], b1[nt]);
            }
#undef MMA_ONE
        }

        buf++;
        if (buf == NBUF) buf = 0;
    }

    // ---------------- epilogue ----------------
    const int orow = R + warpN;
#pragma unroll
    for (int mt = 0; mt < 4; mt++) {
        int co = warpM * 64 + mt * 16 + gid;
        float* base = out + (((size_t)b * COUT + co) * OH + orow) * OW;
#pragma unroll
        for (int nt = 0; nt < 4; nt++) {
            int ow0 = nt * 8 + tig * 2;
            *(float2*)(base + ow0) = make_float2(acc[mt][nt][0], acc[mt][nt][1]);
            *(float2*)(base + 8 * OH * OW + ow0) = make_float2(acc[mt][nt][2], acc[mt][nt][3]);
        }
    }
}

extern "C" void kernel_launch(void* const* d_in, const int* in_sizes, int n_in,
                              void* d_out, int out_size) {
    const float* x = (const float*)d_in[0];   // [32,256,64,64]
    const float* w = (const float*)d_in[1];   // [256,256,3,3]
    float* out = (float*)d_out;               // [32,256,32,32]
    (void)in_sizes; (void)n_in; (void)out_size;

    cudaFuncSetAttribute(conv_mma, cudaFuncAttributeMaxDynamicSharedMemorySize, SM_BYTES);

    prep_w<<<(NWA + 255) / 256, 256>>>(w);

    dim3 grid(8, BN);  // 8 row-tiles x 32 batch = 256 CTAs, 512 thr each
    conv_mma<<<grid, 512, SM_BYTES>>>(x, out);
}